// round 8
// baseline (speedup 1.0000x reference)
#include <cuda_runtime.h>
#include <cuda_bf16.h>
#include <mma.h>
#include <cstdint>

using namespace nvcuda;

// Problem constants
#define NUM_PARTS     16
#define ROWS_PER_PART 257
#define M_REAL        4112
#define VAE           768
#define OUTD          1024
#define BATCH         4096

// GEMM tiling: 128x256 block tile, 256 threads (8 warps of 64x64)
#define BM 128
#define BN 256
#define BK 64
#define M_TILES 33
#define M_PAD   (M_TILES * BM)     // 4224
#define GEMM_THREADS 256
#define STAGES 3

#define STRIDE_A (BK + 8)          // 72
#define STRIDE_B (BN + 8)          // 264
#define SMEM_A_BYTES (BM * STRIDE_A * 2)   // 18432
#define SMEM_B_BYTES (BK * STRIDE_B * 2)   // 33792
#define STAGE_BYTES  (SMEM_A_BYTES + SMEM_B_BYTES)   // 52224
#define EPI_BYTES    (BM * BN * 4)                   // 131072
#define PIPE_BYTES   (STAGES * STAGE_BYTES)          // 156672
#define GEMM_SMEM    (EPI_BYTES > PIPE_BYTES ? EPI_BYTES : PIPE_BYTES)

// Device-global scratch (allocation-free)
__device__ __nv_bfloat16 g_A [(size_t)M_PAD * VAE];    // emb bf16, pad rows zero
__device__ __nv_bfloat16 g_W1[(size_t)VAE * OUTD];
__device__ __nv_bfloat16 g_W2[(size_t)OUTD * OUTD];
__device__ __nv_bfloat16 g_H [(size_t)M_PAD * OUTD];   // layer-1 activations
__device__ __nv_bfloat16 g_Tb[(size_t)M_PAD * OUTD];   // final table (proj+b2), bf16

// ---------------------------------------------------------------------------
__device__ __forceinline__ void cp_async16(void* smem, const void* gmem) {
    unsigned s = (unsigned)__cvta_generic_to_shared(smem);
    asm volatile("cp.async.cg.shared.global [%0], [%1], 16;\n" :: "r"(s), "l"(gmem));
}
__device__ __forceinline__ void cp_commit() { asm volatile("cp.async.commit_group;\n"); }
__device__ __forceinline__ void cp_wait0()  { asm volatile("cp.async.wait_group 0;\n"); }
__device__ __forceinline__ void cp_wait1()  { asm volatile("cp.async.wait_group 1;\n"); }

__device__ __forceinline__ unsigned pack2(float a, float b) {
    __nv_bfloat162 t = __floats2bfloat162_rn(a, b);
    return *reinterpret_cast<unsigned*>(&t);
}
__device__ __forceinline__ float2 bf2f(uint32_t u) {
    __nv_bfloat162 h = *reinterpret_cast<__nv_bfloat162*>(&u);
    return make_float2(__bfloat162float(h.x), __bfloat162float(h.y));
}

// ---------------------------------------------------------------------------
// fp32 -> bf16 one-shot: emb (padded), W1, W2
// ---------------------------------------------------------------------------
__global__ __launch_bounds__(256)
void convert_all(const float* __restrict__ emb,
                 const float* __restrict__ W1,
                 const float* __restrict__ W2)
{
    const int U1 = (M_PAD * VAE) / 4;
    const int U2 = (VAE * OUTD) / 4;
    const int U3 = (OUTD * OUTD) / 4;
    const int UT = U1 + U2 + U3;
    for (int u = blockIdx.x * blockDim.x + threadIdx.x; u < UT;
         u += gridDim.x * blockDim.x) {
        float4 v;
        __nv_bfloat16* dst;
        if (u < U1) {
            int e = u * 4;
            int row = e / VAE;
            if (row < M_REAL) v = *reinterpret_cast<const float4*>(emb + e);
            else              v = make_float4(0.f, 0.f, 0.f, 0.f);
            dst = g_A + e;
        } else if (u < U1 + U2) {
            int e = (u - U1) * 4;
            v = *reinterpret_cast<const float4*>(W1 + e);
            dst = g_W1 + e;
        } else {
            int e = (u - U1 - U2) * 4;
            v = *reinterpret_cast<const float4*>(W2 + e);
            dst = g_W2 + e;
        }
        uint2 p;
        p.x = pack2(v.x, v.y);
        p.y = pack2(v.z, v.w);
        *reinterpret_cast<uint2*>(dst) = p;
    }
}

// ---------------------------------------------------------------------------
// 3-stage pipelined bf16 WMMA GEMM, 64x64 warp tiles.
//   RELU=1: g_H  = relu(g_A @ g_W1 + b1)
//   RELU=0: g_Tb =      g_H @ g_W2 + b2     (pe added in expand)
// ---------------------------------------------------------------------------
template<int K, bool RELU>
__global__ __launch_bounds__(GEMM_THREADS, 1)
void gemm_kern(const float* __restrict__ bias)
{
    extern __shared__ char smem[];
    const __nv_bfloat16* __restrict__ A  = RELU ? g_A  : g_H;
    const __nv_bfloat16* __restrict__ Bw = RELU ? g_W1 : g_W2;
    __nv_bfloat16*       __restrict__ OUT = RELU ? g_H : g_Tb;

    const int t  = threadIdx.x;
    const int m0 = blockIdx.y * BM;
    const int n0 = blockIdx.x * BN;
    const int w  = t >> 5;
    const int wm = (w >> 2) * 64;   // 2 warp-rows (128/64)
    const int wn = (w & 3) * 64;    // 4 warp-cols (256/64)

    wmma::fragment<wmma::accumulator, 16, 16, 16, float> acc[4][4];
    #pragma unroll
    for (int i = 0; i < 4; i++)
        #pragma unroll
        for (int j = 0; j < 4; j++)
            wmma::fill_fragment(acc[i][j], 0.0f);

    auto load_stage = [&](int s, int k0) {
        __nv_bfloat16* sA = (__nv_bfloat16*)(smem + s * STAGE_BYTES);
        __nv_bfloat16* sB = (__nv_bfloat16*)(smem + s * STAGE_BYTES + SMEM_A_BYTES);
        #pragma unroll
        for (int i = 0; i < 4; i++) {               // A: 1024 16B-chunks
            int ch = t + i * GEMM_THREADS;
            int r = ch >> 3, c8 = (ch & 7) * 8;
            cp_async16(sA + r * STRIDE_A + c8,
                       A + (size_t)(m0 + r) * K + k0 + c8);
        }
        #pragma unroll
        for (int i = 0; i < 8; i++) {               // B: 2048 16B-chunks
            int ch = t + i * GEMM_THREADS;
            int r = ch >> 5, c8 = (ch & 31) * 8;
            cp_async16(sB + r * STRIDE_B + c8,
                       Bw + (size_t)(k0 + r) * OUTD + n0 + c8);
        }
        cp_commit();
    };

    constexpr int NIT = K / BK;     // 12 or 16
    load_stage(0, 0);
    load_stage(1, BK);

    #pragma unroll 1
    for (int it = 0; it < NIT; it++) {
        if (it + 1 < NIT) cp_wait1(); else cp_wait0();
        __syncthreads();
        if (it + 2 < NIT) load_stage((it + 2) % STAGES, (it + 2) * BK);

        const int s = it % STAGES;
        const __nv_bfloat16* sA = (const __nv_bfloat16*)(smem + s * STAGE_BYTES);
        const __nv_bfloat16* sB = (const __nv_bfloat16*)(smem + s * STAGE_BYTES + SMEM_A_BYTES);

        #pragma unroll
        for (int kk = 0; kk < BK; kk += 16) {
            wmma::fragment<wmma::matrix_a, 16, 16, 16, __nv_bfloat16, wmma::row_major> af[4];
            wmma::fragment<wmma::matrix_b, 16, 16, 16, __nv_bfloat16, wmma::row_major> bfr[4];
            #pragma unroll
            for (int i = 0; i < 4; i++)
                wmma::load_matrix_sync(af[i], sA + (wm + 16 * i) * STRIDE_A + kk, STRIDE_A);
            #pragma unroll
            for (int j = 0; j < 4; j++)
                wmma::load_matrix_sync(bfr[j], sB + kk * STRIDE_B + wn + 16 * j, STRIDE_B);
            #pragma unroll
            for (int i = 0; i < 4; i++)
                #pragma unroll
                for (int j = 0; j < 4; j++)
                    wmma::mma_sync(acc[i][j], af[i], bfr[j], acc[i][j]);
        }
    }
    __syncthreads();

    // ---- epilogue: accums -> smem fp32 -> +bias (relu) -> bf16 gmem ----
    float* sC = (float*)smem;   // 131072 <= GEMM_SMEM
    #pragma unroll
    for (int i = 0; i < 4; i++)
        #pragma unroll
        for (int j = 0; j < 4; j++)
            wmma::store_matrix_sync(sC + (wm + 16 * i) * BN + wn + 16 * j,
                                    acc[i][j], BN, wmma::mem_row_major);
    __syncthreads();

    const int c4 = t & 63;             // 64 float4-columns span BN=256
    const int gc = n0 + c4 * 4;
    const float4 bias4 = *reinterpret_cast<const float4*>(bias + gc);

    #pragma unroll
    for (int i = 0; i < 32; i++) {
        int r  = (t >> 6) + i * 4;     // 0..127
        int gr = m0 + r;
        float4 v = *reinterpret_cast<const float4*>(sC + r * BN + c4 * 4);
        v.x += bias4.x; v.y += bias4.y; v.z += bias4.z; v.w += bias4.w;
        if (RELU) {
            v.x = fmaxf(v.x, 0.f); v.y = fmaxf(v.y, 0.f);
            v.z = fmaxf(v.z, 0.f); v.w = fmaxf(v.w, 0.f);
        }
        uint2 p;
        p.x = pack2(v.x, v.y);
        p.y = pack2(v.z, v.w);
        *reinterpret_cast<uint2*>(OUT + (size_t)gr * OUTD + gc) = p;
    }
}

// ---------------------------------------------------------------------------
// Expand: out[b,p,:] = float(g_Tb[hash+257p, :]) + pe[p,:]
// Warp per (b,p) row: 4 x uint4 bf16 table reads (2KB/row through L2),
// pe (64KB, L1/L2-resident) added in fp32, streaming fp32 stores.
// ---------------------------------------------------------------------------
#define EXP_BLOCKS  1184
#define EXP_THREADS 256
#define EXP_WARPS   (EXP_BLOCKS * (EXP_THREADS / 32))

__global__ __launch_bounds__(EXP_THREADS)
void expand_kernel(const int* __restrict__ hashes, const float* __restrict__ pe,
                   float* __restrict__ out)
{
    const int warp = blockIdx.x * (EXP_THREADS / 32) + (threadIdx.x >> 5);
    const int lane = threadIdx.x & 31;
    float4* __restrict__ o4 = reinterpret_cast<float4*>(out);

    #pragma unroll 1
    for (int bp = warp; bp < BATCH * NUM_PARTS; bp += EXP_WARPS) {
        const int p = bp & (NUM_PARTS - 1);
        const int h = __ldg(hashes + bp);
        const uint4* __restrict__ src = reinterpret_cast<const uint4*>(
            g_Tb + (size_t)(h + p * ROWS_PER_PART) * OUTD);
        const float4* __restrict__ per = reinterpret_cast<const float4*>(
            pe + (size_t)p * OUTD);

        uint4 tv[4]; float4 pa[4], pb[4];
        #pragma unroll
        for (int j = 0; j < 4; j++) {
            int ch = lane + 32 * j;            // 0..127, 8 bf16 each
            tv[j] = __ldg(src + ch);
            pa[j] = __ldg(per + 2 * ch);
            pb[j] = __ldg(per + 2 * ch + 1);
        }
        float4* dst = o4 + (size_t)bp * (OUTD / 4);
        #pragma unroll
        for (int j = 0; j < 4; j++) {
            int ch = lane + 32 * j;
            float2 f0 = bf2f(tv[j].x), f1 = bf2f(tv[j].y);
            float2 f2 = bf2f(tv[j].z), f3 = bf2f(tv[j].w);
            float4 o0 = make_float4(f0.x + pa[j].x, f0.y + pa[j].y,
                                    f1.x + pa[j].z, f1.y + pa[j].w);
            float4 o1 = make_float4(f2.x + pb[j].x, f2.y + pb[j].y,
                                    f3.x + pb[j].z, f3.y + pb[j].w);
            __stcs(dst + 2 * ch,     o0);
            __stcs(dst + 2 * ch + 1, o1);
        }
    }
}

// ---------------------------------------------------------------------------
extern "C" void kernel_launch(void* const* d_in, const int* in_sizes, int n_in,
                              void* d_out, int out_size)
{
    const int*   hashes = nullptr;
    const float* emb = nullptr; const float* W1 = nullptr; const float* W2 = nullptr;
    const float* pe  = nullptr; const float* b1 = nullptr; const float* b2 = nullptr;
    for (int i = 0; i < n_in; i++) {
        switch (in_sizes[i]) {
            case BATCH * NUM_PARTS: hashes = (const int*)d_in[i];   break;
            case M_REAL * VAE:      emb    = (const float*)d_in[i]; break;
            case VAE * OUTD:        W1     = (const float*)d_in[i]; break;
            case OUTD * OUTD:       W2     = (const float*)d_in[i]; break;
            case NUM_PARTS * OUTD:  pe     = (const float*)d_in[i]; break;
            case OUTD:
                if (!b1) b1 = (const float*)d_in[i]; else b2 = (const float*)d_in[i];
                break;
            default: break;
        }
    }
    float* out = (float*)d_out;

    cudaFuncSetAttribute(gemm_kern<VAE,  true >,
                         cudaFuncAttributeMaxDynamicSharedMemorySize, GEMM_SMEM);
    cudaFuncSetAttribute(gemm_kern<OUTD, false>,
                         cudaFuncAttributeMaxDynamicSharedMemorySize, GEMM_SMEM);

    convert_all<<<2048, 256>>>(emb, W1, W2);
    gemm_kern<VAE,  true ><<<dim3(OUTD / BN, M_TILES), GEMM_THREADS, GEMM_SMEM>>>(b1);
    gemm_kern<OUTD, false><<<dim3(OUTD / BN, M_TILES), GEMM_THREADS, GEMM_SMEM>>>(b2);
    expand_kernel<<<EXP_BLOCKS, EXP_THREADS>>>(hashes, pe, out);
    (void)out_size;
}

// round 11
// speedup vs baseline: 1.0065x; 1.0065x over previous
#include <cuda_runtime.h>
#include <cuda_bf16.h>
#include <mma.h>
#include <cstdint>

using namespace nvcuda;

// Problem constants
#define NUM_PARTS     16
#define ROWS_PER_PART 257
#define M_REAL        4112
#define VAE           768
#define OUTD          1024
#define BATCH         4096

// GEMM tiling: 128x256 block tile, 256 threads (8 warps of 64x64)
#define BM 128
#define BN 256
#define BK 64
#define M_TILES 33
#define M_PAD   (M_TILES * BM)     // 4224
#define GEMM_THREADS 256
#define STAGES 3

#define STRIDE_A (BK + 8)          // 72
#define STRIDE_B (BN + 8)          // 264
#define SMEM_A_BYTES (BM * STRIDE_A * 2)   // 18432
#define SMEM_B_BYTES (BK * STRIDE_B * 2)   // 33792
#define STAGE_BYTES  (SMEM_A_BYTES + SMEM_B_BYTES)   // 52224
#define EPI_BYTES    (BM * BN * 4)                   // 131072
#define PIPE_BYTES   (STAGES * STAGE_BYTES)          // 156672
#define GEMM_SMEM    (EPI_BYTES > PIPE_BYTES ? EPI_BYTES : PIPE_BYTES)

// Device-global scratch (allocation-free)
__device__ __nv_bfloat16 g_A [(size_t)M_PAD * VAE];    // emb bf16, pad rows zero
__device__ __nv_bfloat16 g_W1[(size_t)VAE * OUTD];
__device__ __nv_bfloat16 g_W2[(size_t)OUTD * OUTD];
__device__ __nv_bfloat16 g_H [(size_t)M_PAD * OUTD];   // layer-1 activations
__device__ __nv_bfloat16 g_Tb[(size_t)M_PAD * OUTD];   // final table (proj+b2), bf16

// ---------------------------------------------------------------------------
__device__ __forceinline__ void cp_async16(void* smem, const void* gmem) {
    unsigned s = (unsigned)__cvta_generic_to_shared(smem);
    asm volatile("cp.async.cg.shared.global [%0], [%1], 16;\n" :: "r"(s), "l"(gmem));
}
__device__ __forceinline__ void cp_commit() { asm volatile("cp.async.commit_group;\n"); }
__device__ __forceinline__ void cp_wait0()  { asm volatile("cp.async.wait_group 0;\n"); }
__device__ __forceinline__ void cp_wait1()  { asm volatile("cp.async.wait_group 1;\n"); }

__device__ __forceinline__ unsigned pack2(float a, float b) {
    __nv_bfloat162 t = __floats2bfloat162_rn(a, b);
    return *reinterpret_cast<unsigned*>(&t);
}
__device__ __forceinline__ float2 bf2f(uint32_t u) {
    __nv_bfloat162 h = *reinterpret_cast<__nv_bfloat162*>(&u);
    return make_float2(__bfloat162float(h.x), __bfloat162float(h.y));
}

// ---------------------------------------------------------------------------
// fp32 -> bf16 one-shot: emb (padded), W1, W2
// ---------------------------------------------------------------------------
__global__ __launch_bounds__(256)
void convert_all(const float* __restrict__ emb,
                 const float* __restrict__ W1,
                 const float* __restrict__ W2)
{
    const int U1 = (M_PAD * VAE) / 4;
    const int U2 = (VAE * OUTD) / 4;
    const int U3 = (OUTD * OUTD) / 4;
    const int UT = U1 + U2 + U3;
    for (int u = blockIdx.x * blockDim.x + threadIdx.x; u < UT;
         u += gridDim.x * blockDim.x) {
        float4 v;
        __nv_bfloat16* dst;
        if (u < U1) {
            int e = u * 4;
            int row = e / VAE;
            if (row < M_REAL) v = *reinterpret_cast<const float4*>(emb + e);
            else              v = make_float4(0.f, 0.f, 0.f, 0.f);
            dst = g_A + e;
        } else if (u < U1 + U2) {
            int e = (u - U1) * 4;
            v = *reinterpret_cast<const float4*>(W1 + e);
            dst = g_W1 + e;
        } else {
            int e = (u - U1 - U2) * 4;
            v = *reinterpret_cast<const float4*>(W2 + e);
            dst = g_W2 + e;
        }
        uint2 p;
        p.x = pack2(v.x, v.y);
        p.y = pack2(v.z, v.w);
        *reinterpret_cast<uint2*>(dst) = p;
    }
}

// ---------------------------------------------------------------------------
// 3-stage pipelined bf16 WMMA GEMM, 64x64 warp tiles.
//   RELU=1: g_H  = relu(g_A @ g_W1 + b1)
//   RELU=0: g_Tb =      g_H @ g_W2 + b2     (pe added in expand)
// ---------------------------------------------------------------------------
template<int K, bool RELU>
__global__ __launch_bounds__(GEMM_THREADS, 1)
void gemm_kern(const float* __restrict__ bias)
{
    extern __shared__ char smem[];
    const __nv_bfloat16* __restrict__ A  = RELU ? g_A  : g_H;
    const __nv_bfloat16* __restrict__ Bw = RELU ? g_W1 : g_W2;
    __nv_bfloat16*       __restrict__ OUT = RELU ? g_H : g_Tb;

    const int t  = threadIdx.x;
    const int m0 = blockIdx.y * BM;
    const int n0 = blockIdx.x * BN;
    const int w  = t >> 5;
    const int wm = (w >> 2) * 64;   // 2 warp-rows (128/64)
    const int wn = (w & 3) * 64;    // 4 warp-cols (256/64)

    wmma::fragment<wmma::accumulator, 16, 16, 16, float> acc[4][4];
    #pragma unroll
    for (int i = 0; i < 4; i++)
        #pragma unroll
        for (int j = 0; j < 4; j++)
            wmma::fill_fragment(acc[i][j], 0.0f);

    auto load_stage = [&](int s, int k0) {
        __nv_bfloat16* sA = (__nv_bfloat16*)(smem + s * STAGE_BYTES);
        __nv_bfloat16* sB = (__nv_bfloat16*)(smem + s * STAGE_BYTES + SMEM_A_BYTES);
        #pragma unroll
        for (int i = 0; i < 4; i++) {               // A: 1024 16B-chunks
            int ch = t + i * GEMM_THREADS;
            int r = ch >> 3, c8 = (ch & 7) * 8;
            cp_async16(sA + r * STRIDE_A + c8,
                       A + (size_t)(m0 + r) * K + k0 + c8);
        }
        #pragma unroll
        for (int i = 0; i < 8; i++) {               // B: 2048 16B-chunks
            int ch = t + i * GEMM_THREADS;
            int r = ch >> 5, c8 = (ch & 31) * 8;
            cp_async16(sB + r * STRIDE_B + c8,
                       Bw + (size_t)(k0 + r) * OUTD + n0 + c8);
        }
        cp_commit();
    };

    constexpr int NIT = K / BK;     // 12 or 16
    load_stage(0, 0);
    load_stage(1, BK);

    #pragma unroll 1
    for (int it = 0; it < NIT; it++) {
        if (it + 1 < NIT) cp_wait1(); else cp_wait0();
        __syncthreads();
        if (it + 2 < NIT) load_stage((it + 2) % STAGES, (it + 2) * BK);

        const int s = it % STAGES;
        const __nv_bfloat16* sA = (const __nv_bfloat16*)(smem + s * STAGE_BYTES);
        const __nv_bfloat16* sB = (const __nv_bfloat16*)(smem + s * STAGE_BYTES + SMEM_A_BYTES);

        #pragma unroll
        for (int kk = 0; kk < BK; kk += 16) {
            wmma::fragment<wmma::matrix_a, 16, 16, 16, __nv_bfloat16, wmma::row_major> af[4];
            wmma::fragment<wmma::matrix_b, 16, 16, 16, __nv_bfloat16, wmma::row_major> bfr[4];
            #pragma unroll
            for (int i = 0; i < 4; i++)
                wmma::load_matrix_sync(af[i], sA + (wm + 16 * i) * STRIDE_A + kk, STRIDE_A);
            #pragma unroll
            for (int j = 0; j < 4; j++)
                wmma::load_matrix_sync(bfr[j], sB + kk * STRIDE_B + wn + 16 * j, STRIDE_B);
            #pragma unroll
            for (int i = 0; i < 4; i++)
                #pragma unroll
                for (int j = 0; j < 4; j++)
                    wmma::mma_sync(acc[i][j], af[i], bfr[j], acc[i][j]);
        }
    }
    __syncthreads();

    // ---- epilogue: accums -> smem fp32 -> +bias (relu) -> bf16 gmem ----
    float* sC = (float*)smem;   // 131072 <= GEMM_SMEM
    #pragma unroll
    for (int i = 0; i < 4; i++)
        #pragma unroll
        for (int j = 0; j < 4; j++)
            wmma::store_matrix_sync(sC + (wm + 16 * i) * BN + wn + 16 * j,
                                    acc[i][j], BN, wmma::mem_row_major);
    __syncthreads();

    const int c4 = t & 63;             // 64 float4-columns span BN=256
    const int gc = n0 + c4 * 4;
    const float4 bias4 = *reinterpret_cast<const float4*>(bias + gc);

    #pragma unroll
    for (int i = 0; i < 32; i++) {
        int r  = (t >> 6) + i * 4;     // 0..127
        int gr = m0 + r;
        float4 v = *reinterpret_cast<const float4*>(sC + r * BN + c4 * 4);
        v.x += bias4.x; v.y += bias4.y; v.z += bias4.z; v.w += bias4.w;
        if (RELU) {
            v.x = fmaxf(v.x, 0.f); v.y = fmaxf(v.y, 0.f);
            v.z = fmaxf(v.z, 0.f); v.w = fmaxf(v.w, 0.f);
        }
        uint2 p;
        p.x = pack2(v.x, v.y);
        p.y = pack2(v.z, v.w);
        *reinterpret_cast<uint2*>(OUT + (size_t)gr * OUTD + gc) = p;
    }
}

// ---------------------------------------------------------------------------
// Expand: out[b,p,:] = float(g_Tb[hash+257p, :]) + pe[p,:]
// Warp per (b,p) row. EXP_WARPS % 16 == 0 => p is warp-invariant: the pe row
// slice (32 floats/lane) is hoisted into registers ONCE, zero in-loop pe loads.
// Per row: 4 bf16 uint4 table loads (2KB via L2) + 8 streaming float4 stores.
// ---------------------------------------------------------------------------
#define EXP_BLOCKS  1184
#define EXP_THREADS 256
#define EXP_WARPS   (EXP_BLOCKS * (EXP_THREADS / 32))   // 9472 = 16 * 592

__global__ __launch_bounds__(EXP_THREADS)
void expand_kernel(const int* __restrict__ hashes, const float* __restrict__ pe,
                   float* __restrict__ out)
{
    const int warp = blockIdx.x * (EXP_THREADS / 32) + (threadIdx.x >> 5);
    const int lane = threadIdx.x & 31;
    const int p    = warp & (NUM_PARTS - 1);       // invariant over the loop
    float4* __restrict__ o4 = reinterpret_cast<float4*>(out);

    // hoist pe[p, :] slice for this lane: chunks ch = lane + 32j, j=0..3,
    // each chunk covers 8 floats -> pa[j] (first 4), pb[j] (last 4).
    const float4* __restrict__ per = reinterpret_cast<const float4*>(
        pe + (size_t)p * OUTD);
    float4 pa[4], pb[4];
    #pragma unroll
    for (int j = 0; j < 4; j++) {
        int ch = lane + 32 * j;
        pa[j] = __ldg(per + 2 * ch);
        pb[j] = __ldg(per + 2 * ch + 1);
    }

    #pragma unroll 1
    for (int bp = warp; bp < BATCH * NUM_PARTS; bp += EXP_WARPS) {
        const int h = __ldg(hashes + bp);
        const uint4* __restrict__ src = reinterpret_cast<const uint4*>(
            g_Tb + (size_t)(h + p * ROWS_PER_PART) * OUTD);

        uint4 tv[4];
        #pragma unroll
        for (int j = 0; j < 4; j++)
            tv[j] = __ldg(src + lane + 32 * j);

        float4* dst = o4 + (size_t)bp * (OUTD / 4);
        #pragma unroll
        for (int j = 0; j < 4; j++) {
            int ch = lane + 32 * j;
            float2 f0 = bf2f(tv[j].x), f1 = bf2f(tv[j].y);
            float2 f2 = bf2f(tv[j].z), f3 = bf2f(tv[j].w);
            float4 o0 = make_float4(f0.x + pa[j].x, f0.y + pa[j].y,
                                    f1.x + pa[j].z, f1.y + pa[j].w);
            float4 o1 = make_float4(f2.x + pb[j].x, f2.y + pb[j].y,
                                    f3.x + pb[j].z, f3.y + pb[j].w);
            __stcs(dst + 2 * ch,     o0);
            __stcs(dst + 2 * ch + 1, o1);
        }
    }
}

// ---------------------------------------------------------------------------
extern "C" void kernel_launch(void* const* d_in, const int* in_sizes, int n_in,
                              void* d_out, int out_size)
{
    const int*   hashes = nullptr;
    const float* emb = nullptr; const float* W1 = nullptr; const float* W2 = nullptr;
    const float* pe  = nullptr; const float* b1 = nullptr; const float* b2 = nullptr;
    for (int i = 0; i < n_in; i++) {
        switch (in_sizes[i]) {
            case BATCH * NUM_PARTS: hashes = (const int*)d_in[i];   break;
            case M_REAL * VAE:      emb    = (const float*)d_in[i]; break;
            case VAE * OUTD:        W1     = (const float*)d_in[i]; break;
            case OUTD * OUTD:       W2     = (const float*)d_in[i]; break;
            case NUM_PARTS * OUTD:  pe     = (const float*)d_in[i]; break;
            case OUTD:
                if (!b1) b1 = (const float*)d_in[i]; else b2 = (const float*)d_in[i];
                break;
            default: break;
        }
    }
    float* out = (float*)d_out;

    cudaFuncSetAttribute(gemm_kern<VAE,  true >,
                         cudaFuncAttributeMaxDynamicSharedMemorySize, GEMM_SMEM);
    cudaFuncSetAttribute(gemm_kern<OUTD, false>,
                         cudaFuncAttributeMaxDynamicSharedMemorySize, GEMM_SMEM);

    convert_all<<<2048, 256>>>(emb, W1, W2);
    gemm_kern<VAE,  true ><<<dim3(OUTD / BN, M_TILES), GEMM_THREADS, GEMM_SMEM>>>(b1);
    gemm_kern<OUTD, false><<<dim3(OUTD / BN, M_TILES), GEMM_THREADS, GEMM_SMEM>>>(b2);
    expand_kernel<<<EXP_BLOCKS, EXP_THREADS>>>(hashes, pe, out);
    (void)out_size;
}

// round 14
// speedup vs baseline: 1.3105x; 1.3020x over previous
#include <cuda_runtime.h>
#include <cuda_bf16.h>
#include <mma.h>
#include <cstdint>

using namespace nvcuda;

// Problem constants
#define NUM_PARTS     16
#define ROWS_PER_PART 257
#define M_REAL        4112
#define VAE           768
#define OUTD          1024
#define BATCH         4096

// GEMM tiling: 128x256 block tile, 256 threads (8 warps of 64x64)
#define BM 128
#define BN 256
#define BK 64
#define M_TILES 33
#define M_PAD   (M_TILES * BM)     // 4224
#define GEMM_THREADS 256
#define STAGES 3

#define STRIDE_A (BK + 8)          // 72
#define STRIDE_B (BN + 8)          // 264
#define SMEM_A_BYTES (BM * STRIDE_A * 2)   // 18432
#define SMEM_B_BYTES (BK * STRIDE_B * 2)   // 33792
#define STAGE_BYTES  (SMEM_A_BYTES + SMEM_B_BYTES)   // 52224
#define EPI_BYTES    (BM * BN * 4)                   // 131072
#define PIPE_BYTES   (STAGES * STAGE_BYTES)          // 156672
#define GEMM_SMEM    (EPI_BYTES > PIPE_BYTES ? EPI_BYTES : PIPE_BYTES)

// Device-global scratch (allocation-free)
__device__ __nv_bfloat16 g_A [(size_t)M_PAD * VAE];    // emb bf16, pad rows zero
__device__ __nv_bfloat16 g_W1[(size_t)VAE * OUTD];
__device__ __nv_bfloat16 g_W2[(size_t)OUTD * OUTD];
__device__ __nv_bfloat16 g_H [(size_t)M_PAD * OUTD];   // layer-1 activations
__device__ __nv_bfloat16 g_Tb[(size_t)M_PAD * OUTD];   // final table (proj+b2), bf16

// ---------------------------------------------------------------------------
__device__ __forceinline__ void cp_async16(void* smem, const void* gmem) {
    unsigned s = (unsigned)__cvta_generic_to_shared(smem);
    asm volatile("cp.async.cg.shared.global [%0], [%1], 16;\n" :: "r"(s), "l"(gmem));
}
__device__ __forceinline__ void cp_commit() { asm volatile("cp.async.commit_group;\n"); }
__device__ __forceinline__ void cp_wait0()  { asm volatile("cp.async.wait_group 0;\n"); }
__device__ __forceinline__ void cp_wait1()  { asm volatile("cp.async.wait_group 1;\n"); }

__device__ __forceinline__ unsigned pack2(float a, float b) {
    __nv_bfloat162 t = __floats2bfloat162_rn(a, b);
    return *reinterpret_cast<unsigned*>(&t);
}
__device__ __forceinline__ float2 bf2f(uint32_t u) {
    __nv_bfloat162 h = *reinterpret_cast<__nv_bfloat162*>(&u);
    return make_float2(__bfloat162float(h.x), __bfloat162float(h.y));
}

// ---------------------------------------------------------------------------
// fp32 -> bf16 one-shot: emb (padded), W1, W2
// ---------------------------------------------------------------------------
__global__ __launch_bounds__(256)
void convert_all(const float* __restrict__ emb,
                 const float* __restrict__ W1,
                 const float* __restrict__ W2)
{
    const int U1 = (M_PAD * VAE) / 4;
    const int U2 = (VAE * OUTD) / 4;
    const int U3 = (OUTD * OUTD) / 4;
    const int UT = U1 + U2 + U3;
    for (int u = blockIdx.x * blockDim.x + threadIdx.x; u < UT;
         u += gridDim.x * blockDim.x) {
        float4 v;
        __nv_bfloat16* dst;
        if (u < U1) {
            int e = u * 4;
            int row = e / VAE;
            if (row < M_REAL) v = *reinterpret_cast<const float4*>(emb + e);
            else              v = make_float4(0.f, 0.f, 0.f, 0.f);
            dst = g_A + e;
        } else if (u < U1 + U2) {
            int e = (u - U1) * 4;
            v = *reinterpret_cast<const float4*>(W1 + e);
            dst = g_W1 + e;
        } else {
            int e = (u - U1 - U2) * 4;
            v = *reinterpret_cast<const float4*>(W2 + e);
            dst = g_W2 + e;
        }
        uint2 p;
        p.x = pack2(v.x, v.y);
        p.y = pack2(v.z, v.w);
        *reinterpret_cast<uint2*>(dst) = p;
    }
}

// ---------------------------------------------------------------------------
// 3-stage pipelined bf16 WMMA GEMM, 64x64 warp tiles.
//   RELU=1: g_H  = relu(g_A @ g_W1 + b1)
//   RELU=0: g_Tb =      g_H @ g_W2 + b2     (pe added in expand)
// ---------------------------------------------------------------------------
template<int K, bool RELU>
__global__ __launch_bounds__(GEMM_THREADS, 1)
void gemm_kern(const float* __restrict__ bias)
{
    extern __shared__ char smem[];
    const __nv_bfloat16* __restrict__ A  = RELU ? g_A  : g_H;
    const __nv_bfloat16* __restrict__ Bw = RELU ? g_W1 : g_W2;
    __nv_bfloat16*       __restrict__ OUT = RELU ? g_H : g_Tb;

    const int t  = threadIdx.x;
    const int m0 = blockIdx.y * BM;
    const int n0 = blockIdx.x * BN;
    const int w  = t >> 5;
    const int wm = (w >> 2) * 64;   // 2 warp-rows (128/64)
    const int wn = (w & 3) * 64;    // 4 warp-cols (256/64)

    wmma::fragment<wmma::accumulator, 16, 16, 16, float> acc[4][4];
    #pragma unroll
    for (int i = 0; i < 4; i++)
        #pragma unroll
        for (int j = 0; j < 4; j++)
            wmma::fill_fragment(acc[i][j], 0.0f);

    auto load_stage = [&](int s, int k0) {
        __nv_bfloat16* sA = (__nv_bfloat16*)(smem + s * STAGE_BYTES);
        __nv_bfloat16* sB = (__nv_bfloat16*)(smem + s * STAGE_BYTES + SMEM_A_BYTES);
        #pragma unroll
        for (int i = 0; i < 4; i++) {               // A: 1024 16B-chunks
            int ch = t + i * GEMM_THREADS;
            int r = ch >> 3, c8 = (ch & 7) * 8;
            cp_async16(sA + r * STRIDE_A + c8,
                       A + (size_t)(m0 + r) * K + k0 + c8);
        }
        #pragma unroll
        for (int i = 0; i < 8; i++) {               // B: 2048 16B-chunks
            int ch = t + i * GEMM_THREADS;
            int r = ch >> 5, c8 = (ch & 31) * 8;
            cp_async16(sB + r * STRIDE_B + c8,
                       Bw + (size_t)(k0 + r) * OUTD + n0 + c8);
        }
        cp_commit();
    };

    constexpr int NIT = K / BK;     // 12 or 16
    load_stage(0, 0);
    load_stage(1, BK);

    #pragma unroll 1
    for (int it = 0; it < NIT; it++) {
        if (it + 1 < NIT) cp_wait1(); else cp_wait0();
        __syncthreads();
        if (it + 2 < NIT) load_stage((it + 2) % STAGES, (it + 2) * BK);

        const int s = it % STAGES;
        const __nv_bfloat16* sA = (const __nv_bfloat16*)(smem + s * STAGE_BYTES);
        const __nv_bfloat16* sB = (const __nv_bfloat16*)(smem + s * STAGE_BYTES + SMEM_A_BYTES);

        #pragma unroll
        for (int kk = 0; kk < BK; kk += 16) {
            wmma::fragment<wmma::matrix_a, 16, 16, 16, __nv_bfloat16, wmma::row_major> af[4];
            wmma::fragment<wmma::matrix_b, 16, 16, 16, __nv_bfloat16, wmma::row_major> bfr[4];
            #pragma unroll
            for (int i = 0; i < 4; i++)
                wmma::load_matrix_sync(af[i], sA + (wm + 16 * i) * STRIDE_A + kk, STRIDE_A);
            #pragma unroll
            for (int j = 0; j < 4; j++)
                wmma::load_matrix_sync(bfr[j], sB + kk * STRIDE_B + wn + 16 * j, STRIDE_B);
            #pragma unroll
            for (int i = 0; i < 4; i++)
                #pragma unroll
                for (int j = 0; j < 4; j++)
                    wmma::mma_sync(acc[i][j], af[i], bfr[j], acc[i][j]);
        }
    }
    __syncthreads();

    // ---- epilogue: accums -> smem fp32 -> +bias (relu) -> bf16 gmem ----
    float* sC = (float*)smem;   // 131072 <= GEMM_SMEM
    #pragma unroll
    for (int i = 0; i < 4; i++)
        #pragma unroll
        for (int j = 0; j < 4; j++)
            wmma::store_matrix_sync(sC + (wm + 16 * i) * BN + wn + 16 * j,
                                    acc[i][j], BN, wmma::mem_row_major);
    __syncthreads();

    const int c4 = t & 63;             // 64 float4-columns span BN=256
    const int gc = n0 + c4 * 4;
    const float4 bias4 = *reinterpret_cast<const float4*>(bias + gc);

    #pragma unroll
    for (int i = 0; i < 32; i++) {
        int r  = (t >> 6) + i * 4;     // 0..127
        int gr = m0 + r;
        float4 v = *reinterpret_cast<const float4*>(sC + r * BN + c4 * 4);
        v.x += bias4.x; v.y += bias4.y; v.z += bias4.z; v.w += bias4.w;
        if (RELU) {
            v.x = fmaxf(v.x, 0.f); v.y = fmaxf(v.y, 0.f);
            v.z = fmaxf(v.z, 0.f); v.w = fmaxf(v.w, 0.f);
        }
        uint2 p;
        p.x = pack2(v.x, v.y);
        p.y = pack2(v.z, v.w);
        *reinterpret_cast<uint2*>(OUT + (size_t)gr * OUTD + gc) = p;
    }
}

// ---------------------------------------------------------------------------
// Expand: out[b,p,:] = float(g_Tb[hash+257p, :]) + pe[p,:]
// Warp per (b,p) row, CONTIGUOUS addressing by output chunk ch = lane + 32j:
//   - table read: uint2 (8B = 4 bf16 = one output float4) at src2+ch
//     -> 256B/warp/instr, coalesced
//   - store: float4 at dst+ch -> 512B/warp/instr, contiguous
//   - pe[p] slice hoisted to 8 float4 regs (p is warp-invariant since
//     EXP_WARPS % 16 == 0)
// ---------------------------------------------------------------------------
#define EXP_BLOCKS  1184
#define EXP_THREADS 256
#define EXP_WARPS   (EXP_BLOCKS * (EXP_THREADS / 32))   // 9472 = 16 * 592

__global__ __launch_bounds__(EXP_THREADS)
void expand_kernel(const int* __restrict__ hashes, const float* __restrict__ pe,
                   float* __restrict__ out)
{
    const int warp = blockIdx.x * (EXP_THREADS / 32) + (threadIdx.x >> 5);
    const int lane = threadIdx.x & 31;
    const int p    = warp & (NUM_PARTS - 1);       // invariant over the loop
    float4* __restrict__ o4 = reinterpret_cast<float4*>(out);

    // hoist pe[p, :] slice: chunk ch = lane + 32j covers floats [4ch, 4ch+4)
    const float4* __restrict__ per = reinterpret_cast<const float4*>(
        pe + (size_t)p * OUTD);
    float4 pv[8];
    #pragma unroll
    for (int j = 0; j < 8; j++)
        pv[j] = __ldg(per + lane + 32 * j);

    #pragma unroll 1
    for (int bp = warp; bp < BATCH * NUM_PARTS; bp += EXP_WARPS) {
        const int h = __ldg(hashes + bp);
        const uint2* __restrict__ src2 = reinterpret_cast<const uint2*>(
            g_Tb + (size_t)(h + p * ROWS_PER_PART) * OUTD);

        uint2 tv[8];
        #pragma unroll
        for (int j = 0; j < 8; j++)
            tv[j] = __ldg(src2 + lane + 32 * j);

        float4* dst = o4 + (size_t)bp * (OUTD / 4);
        #pragma unroll
        for (int j = 0; j < 8; j++) {
            float2 lo = bf2f(tv[j].x), hi = bf2f(tv[j].y);
            float4 o = make_float4(lo.x + pv[j].x, lo.y + pv[j].y,
                                   hi.x + pv[j].z, hi.y + pv[j].w);
            __stcs(dst + lane + 32 * j, o);
        }
    }
}

// ---------------------------------------------------------------------------
extern "C" void kernel_launch(void* const* d_in, const int* in_sizes, int n_in,
                              void* d_out, int out_size)
{
    const int*   hashes = nullptr;
    const float* emb = nullptr; const float* W1 = nullptr; const float* W2 = nullptr;
    const float* pe  = nullptr; const float* b1 = nullptr; const float* b2 = nullptr;
    for (int i = 0; i < n_in; i++) {
        switch (in_sizes[i]) {
            case BATCH * NUM_PARTS: hashes = (const int*)d_in[i];   break;
            case M_REAL * VAE:      emb    = (const float*)d_in[i]; break;
            case VAE * OUTD:        W1     = (const float*)d_in[i]; break;
            case OUTD * OUTD:       W2     = (const float*)d_in[i]; break;
            case NUM_PARTS * OUTD:  pe     = (const float*)d_in[i]; break;
            case OUTD:
                if (!b1) b1 = (const float*)d_in[i]; else b2 = (const float*)d_in[i];
                break;
            default: break;
        }
    }
    float* out = (float*)d_out;

    cudaFuncSetAttribute(gemm_kern<VAE,  true >,
                         cudaFuncAttributeMaxDynamicSharedMemorySize, GEMM_SMEM);
    cudaFuncSetAttribute(gemm_kern<OUTD, false>,
                         cudaFuncAttributeMaxDynamicSharedMemorySize, GEMM_SMEM);

    convert_all<<<2048, 256>>>(emb, W1, W2);
    gemm_kern<VAE,  true ><<<dim3(OUTD / BN, M_TILES), GEMM_THREADS, GEMM_SMEM>>>(b1);
    gemm_kern<OUTD, false><<<dim3(OUTD / BN, M_TILES), GEMM_THREADS, GEMM_SMEM>>>(b2);
    expand_kernel<<<EXP_BLOCKS, EXP_THREADS>>>(hashes, pe, out);
    (void)out_size;
}